// round 10
// baseline (speedup 1.0000x reference)
#include <cuda_runtime.h>
#include <cstdint>
#include <math.h>

#define Bb 64
#define Tt 256
#define Hh 768
#define KB 16

// ---------------- packed f32x2 helpers (sm_100+ base PTX, not 'a'-gated) -----
__device__ __forceinline__ void ffma2(uint64_t& d, uint64_t a, uint64_t b) {
    asm("fma.rn.f32x2 %0, %1, %2, %0;" : "+l"(d) : "l"(a), "l"(b));
}
__device__ __forceinline__ uint64_t bcast2(float x) {
    uint64_t r;
    asm("mov.b64 %0, {%1, %1};" : "=l"(r) : "f"(x));
    return r;
}
__device__ __forceinline__ void unpack2(uint64_t v, float& lo, float& hi) {
    asm("mov.b64 {%0, %1}, %2;" : "=f"(lo), "=f"(hi) : "l"(v));
}
union F4U2 { float4 f; uint64_t u[2]; };

// ---------------- scratch (static device globals; no allocation) -------------
__device__ float g_whqT[(size_t)Bb*Tt*Tt];   // whqT[b][i][j] = whq[b][j][i]
__device__ float g_whp [(size_t)Bb*Tt*Tt];
__device__ float g_pb  [(size_t)Bb*Tt*Hh];
__device__ float g_Sb  [(size_t)Bb*Tt*Tt];
__device__ float g_Sd  [(size_t)Bb*Tt*Tt];
__device__ float g_P   [(size_t)4*Bb*Tt*Tt];
__device__ float g_qWm[Bb*Tt];
__device__ float g_pWm[Bb*Tt];

// ---------------- K0: qWm[b,t] = q[b,t,:]@Wm ; pWm likewise ------------------
__global__ void k_vec(const float* __restrict__ q, const float* __restrict__ p,
                      const float* __restrict__ Wm) {
    int b = blockIdx.y, t = blockIdx.x, tid = threadIdx.x;
    const float* qr = q + ((size_t)b*Tt + t)*Hh;
    const float* pr = p + ((size_t)b*Tt + t)*Hh;
    float sq = 0.f, sp = 0.f;
    for (int h = tid; h < Hh; h += 256) {
        float w = Wm[h];
        sq += qr[h]*w; sp += pr[h]*w;
    }
    for (int o = 16; o; o >>= 1) {
        sq += __shfl_down_sync(0xffffffffu, sq, o);
        sp += __shfl_down_sync(0xffffffffu, sp, o);
    }
    __shared__ float ssq[8], ssp[8];
    int w = tid >> 5, l = tid & 31;
    if (!l) { ssq[w] = sq; ssp[w] = sp; }
    __syncthreads();
    if (tid == 0) {
        float a = 0.f, c = 0.f;
        for (int i = 0; i < 8; i++) { a += ssq[i]; c += ssp[i]; }
        g_qWm[b*Tt + t] = a;
        g_pWm[b*Tt + t] = c;
    }
}

// ======== unified 128x128-tile batched GEMM, double-buffered =================
// C[z] = A[z](MxK) @ W[z](KxN). A row-major pitch lda; W row-major pitch N.
// z batch: A += z*aStr, W += (z & wMask)*wStr, C += z*cStr.
// trans!=0 -> store C[n*Tt + m].
__global__ void __launch_bounds__(256, 2) gemm128(
    const float* __restrict__ A, size_t aStr, int lda,
    const float* __restrict__ W, size_t wStr, int wMask, int N,
    float* __restrict__ C, size_t cStr, int K, int trans) {
    __shared__ float As[2][KB][132];
    __shared__ float Bs[2][KB][128];
    int z = blockIdx.z;
    int m0 = blockIdx.y * 128, n0 = blockIdx.x * 128;
    const float* Ab = A + (size_t)z * aStr;
    const float* Wb = W + (size_t)(z & wMask) * wStr;
    float* Cb = C + (size_t)z * cStr;

    int tid = threadIdx.x;
    int tx = tid & 15, ty = tid >> 4;
    int arow0 = tid >> 2, ac4 = (tid & 3) * 4;       // A-load mapping (2 iters)
    int krow0 = tid >> 5, bcol4 = (tid & 31) * 4;    // B-load mapping (2 iters)

    float4 pa[2], pb[2];
    #pragma unroll
    for (int i = 0; i < 2; i++) {
        pa[i] = *(const float4*)&Ab[(size_t)(m0 + arow0 + i*64)*lda + ac4];
        pb[i] = *(const float4*)&Wb[(size_t)(krow0 + i*8)*N + n0 + bcol4];
    }
    #pragma unroll
    for (int i = 0; i < 2; i++) {
        int row = arow0 + i*64;
        As[0][ac4+0][row] = pa[i].x; As[0][ac4+1][row] = pa[i].y;
        As[0][ac4+2][row] = pa[i].z; As[0][ac4+3][row] = pa[i].w;
        *(float4*)&Bs[0][krow0 + i*8][bcol4] = pb[i];
    }
    __syncthreads();

    uint64_t acc[8][4] = {};
    int nt = K / KB;
    for (int t = 0; t < nt; t++) {
        int cur = t & 1;
        bool more = (t + 1) < nt;
        if (more) {
            int k0 = (t + 1) * KB;
            #pragma unroll
            for (int i = 0; i < 2; i++) {
                pa[i] = *(const float4*)&Ab[(size_t)(m0 + arow0 + i*64)*lda + k0 + ac4];
                pb[i] = *(const float4*)&Wb[(size_t)(k0 + krow0 + i*8)*N + n0 + bcol4];
            }
        }
        #pragma unroll
        for (int k = 0; k < KB; k++) {
            float4 a0 = *(const float4*)&As[cur][k][ty*4];
            float4 a1 = *(const float4*)&As[cur][k][64 + ty*4];
            F4U2 b0; b0.f = *(const float4*)&Bs[cur][k][tx*4];
            F4U2 b1; b1.f = *(const float4*)&Bs[cur][k][64 + tx*4];
            float am[8] = {a0.x, a0.y, a0.z, a0.w, a1.x, a1.y, a1.z, a1.w};
            #pragma unroll
            for (int mi = 0; mi < 8; mi++) {
                uint64_t aa = bcast2(am[mi]);
                ffma2(acc[mi][0], aa, b0.u[0]);
                ffma2(acc[mi][1], aa, b0.u[1]);
                ffma2(acc[mi][2], aa, b1.u[0]);
                ffma2(acc[mi][3], aa, b1.u[1]);
            }
        }
        if (more) {
            int nb = cur ^ 1;
            #pragma unroll
            for (int i = 0; i < 2; i++) {
                int row = arow0 + i*64;
                As[nb][ac4+0][row] = pa[i].x; As[nb][ac4+1][row] = pa[i].y;
                As[nb][ac4+2][row] = pa[i].z; As[nb][ac4+3][row] = pa[i].w;
                *(float4*)&Bs[nb][krow0 + i*8][bcol4] = pb[i];
            }
            __syncthreads();
        }
    }
    #pragma unroll
    for (int mi = 0; mi < 8; mi++) {
        int m = m0 + ((mi < 4) ? (ty*4 + mi) : (64 + ty*4 + mi - 4));
        #pragma unroll
        for (int np = 0; np < 4; np++) {
            int n = n0 + ((np < 2) ? (tx*4 + 2*np) : (64 + tx*4 + 2*(np - 2)));
            float c0, c1; unpack2(acc[mi][np], c0, c1);
            if (trans) {
                Cb[(size_t)(n + 0)*Tt + m] = c0;
                Cb[(size_t)(n + 1)*Tt + m] = c1;
            } else {
                *(float2*)&Cb[(size_t)m*N + n] = make_float2(c0, c1);
            }
        }
    }
}

// ---- dual NT GEMM (128x64 tile, 8x4/thread), double-buffered ---------------
// Sb = pb@q^T, Sd = tanh((p*Wd)@q^T)*vd
__global__ void __launch_bounds__(256, 2) gemm_bt2(
    const float* __restrict__ p, const float* __restrict__ q,
    const float* __restrict__ Wd, const float* __restrict__ vd) {
    __shared__ float As1[2][KB][132], As2[2][KB][132], Bs[2][KB][68];
    int b = blockIdx.z;
    int m0 = blockIdx.y * 128, n0 = blockIdx.x * 64;
    const float* pbb = g_pb + (size_t)b*Tt*Hh;
    const float* pr  = p   + (size_t)b*Tt*Hh;
    const float* qr  = q   + (size_t)b*Tt*Hh;
    int tid = threadIdx.x;
    int tx = tid & 15, ty = tid >> 4;
    int arow0 = tid >> 2, ac4 = (tid & 3) * 4;
    int brow = tid >> 2, bc4 = (tid & 3) * 4;

    float4 pa1[2], pa2[2], pq;
    #pragma unroll
    for (int i = 0; i < 2; i++) {
        pa1[i] = *(const float4*)&pbb[(size_t)(m0 + arow0 + i*64)*Hh + ac4];
        pa2[i] = *(const float4*)&pr [(size_t)(m0 + arow0 + i*64)*Hh + ac4];
    }
    pq = *(const float4*)&qr[(size_t)(n0 + brow)*Hh + bc4];
    {
        float4 wd = *(const float4*)&Wd[ac4];
        #pragma unroll
        for (int i = 0; i < 2; i++) {
            int row = arow0 + i*64;
            As1[0][ac4+0][row] = pa1[i].x; As1[0][ac4+1][row] = pa1[i].y;
            As1[0][ac4+2][row] = pa1[i].z; As1[0][ac4+3][row] = pa1[i].w;
            As2[0][ac4+0][row] = pa2[i].x*wd.x; As2[0][ac4+1][row] = pa2[i].y*wd.y;
            As2[0][ac4+2][row] = pa2[i].z*wd.z; As2[0][ac4+3][row] = pa2[i].w*wd.w;
        }
        Bs[0][bc4+0][brow] = pq.x; Bs[0][bc4+1][brow] = pq.y;
        Bs[0][bc4+2][brow] = pq.z; Bs[0][bc4+3][brow] = pq.w;
    }
    __syncthreads();

    uint64_t ab[8][2] = {}, ad[8][2] = {};
    int nt = Hh / KB;
    for (int t = 0; t < nt; t++) {
        int cur = t & 1;
        bool more = (t + 1) < nt;
        if (more) {
            int k0 = (t + 1) * KB;
            #pragma unroll
            for (int i = 0; i < 2; i++) {
                pa1[i] = *(const float4*)&pbb[(size_t)(m0 + arow0 + i*64)*Hh + k0 + ac4];
                pa2[i] = *(const float4*)&pr [(size_t)(m0 + arow0 + i*64)*Hh + k0 + ac4];
            }
            pq = *(const float4*)&qr[(size_t)(n0 + brow)*Hh + k0 + bc4];
        }
        #pragma unroll
        for (int k = 0; k < KB; k++) {
            float4 x0 = *(const float4*)&As1[cur][k][ty*4];
            float4 x1 = *(const float4*)&As1[cur][k][64 + ty*4];
            float4 y0 = *(const float4*)&As2[cur][k][ty*4];
            float4 y1 = *(const float4*)&As2[cur][k][64 + ty*4];
            F4U2 bb; bb.f = *(const float4*)&Bs[cur][k][tx*4];
            float am1[8] = {x0.x, x0.y, x0.z, x0.w, x1.x, x1.y, x1.z, x1.w};
            float am2[8] = {y0.x, y0.y, y0.z, y0.w, y1.x, y1.y, y1.z, y1.w};
            #pragma unroll
            for (int mi = 0; mi < 8; mi++) {
                uint64_t aa1 = bcast2(am1[mi]);
                uint64_t aa2 = bcast2(am2[mi]);
                ffma2(ab[mi][0], aa1, bb.u[0]);
                ffma2(ab[mi][1], aa1, bb.u[1]);
                ffma2(ad[mi][0], aa2, bb.u[0]);
                ffma2(ad[mi][1], aa2, bb.u[1]);
            }
        }
        if (more) {
            int nb = cur ^ 1;
            float4 wd = *(const float4*)&Wd[(t + 1)*KB + ac4];
            #pragma unroll
            for (int i = 0; i < 2; i++) {
                int row = arow0 + i*64;
                As1[nb][ac4+0][row] = pa1[i].x; As1[nb][ac4+1][row] = pa1[i].y;
                As1[nb][ac4+2][row] = pa1[i].z; As1[nb][ac4+3][row] = pa1[i].w;
                As2[nb][ac4+0][row] = pa2[i].x*wd.x; As2[nb][ac4+1][row] = pa2[i].y*wd.y;
                As2[nb][ac4+2][row] = pa2[i].z*wd.z; As2[nb][ac4+3][row] = pa2[i].w*wd.w;
            }
            Bs[nb][bc4+0][brow] = pq.x; Bs[nb][bc4+1][brow] = pq.y;
            Bs[nb][bc4+2][brow] = pq.z; Bs[nb][bc4+3][brow] = pq.w;
            __syncthreads();
        }
    }
    size_t base = (size_t)b*Tt*Tt;
    #pragma unroll
    for (int mi = 0; mi < 8; mi++) {
        int m = m0 + ((mi < 4) ? (ty*4 + mi) : (64 + ty*4 + mi - 4));
        #pragma unroll
        for (int np = 0; np < 2; np++) {
            int n = n0 + tx*4 + 2*np;
            float b0, b1; unpack2(ab[mi][np], b0, b1);
            float d0, d1; unpack2(ad[mi][np], d0, d1);
            *(float2*)&g_Sb[base + (size_t)m*Tt + n] = make_float2(b0, b1);
            g_Sd[base + (size_t)m*Tt + n + 0] = tanhf(d0) * vd[n + 0];
            g_Sd[base + (size_t)m*Tt + n + 1] = tanhf(d1) * vd[n + 1];
        }
    }
}

// ---------------- K3: finish scores + row softmax -> g_P ---------------------
__global__ void k_softmax(const float* __restrict__ vc, const float* __restrict__ vm) {
    int mode = blockIdx.z, b = blockIdx.y, i = blockIdx.x, j = threadIdx.x;
    size_t base = (size_t)b*Tt*Tt + (size_t)i*Tt;
    float s;
    if      (mode == 0) s = tanhf(g_whp[base + j] + g_whqT[base + j]) * vc[i];
    else if (mode == 1) s = g_Sb[base + j];
    else if (mode == 2) s = g_Sd[base + j];
    else                s = tanhf(g_qWm[b*Tt + j] - g_pWm[b*Tt + i]) * vm[j];

    float m = s;
    for (int o = 16; o; o >>= 1) m = fmaxf(m, __shfl_xor_sync(0xffffffffu, m, o));
    __shared__ float rm[8], rs[8];
    int w = j >> 5, l = j & 31;
    if (!l) rm[w] = m;
    __syncthreads();
    float mm = rm[0];
    #pragma unroll
    for (int k = 1; k < 8; k++) mm = fmaxf(mm, rm[k]);

    float e = __expf(s - mm);
    float sum = e;
    for (int o = 16; o; o >>= 1) sum += __shfl_xor_sync(0xffffffffu, sum, o);
    if (!l) rs[w] = sum;
    __syncthreads();
    float tot = 0.f;
    #pragma unroll
    for (int k = 0; k < 8; k++) tot += rs[k];

    g_P[(size_t)mode*Bb*Tt*Tt + base + j] = e / tot;
}

// ---------------- launch -----------------------------------------------------
extern "C" void kernel_launch(void* const* d_in, const int* in_sizes, int n_in,
                              void* d_out, int out_size) {
    const float* q   = (const float*)d_in[0];
    const float* p   = (const float*)d_in[1];
    const float* Wc1 = (const float*)d_in[2];
    const float* Wc2 = (const float*)d_in[3];
    const float* vc  = (const float*)d_in[4];
    const float* Wb  = (const float*)d_in[5];
    const float* Wd  = (const float*)d_in[6];
    const float* vd  = (const float*)d_in[7];
    const float* Wm  = (const float*)d_in[8];
    const float* vm  = (const float*)d_in[9];
    float* out = (float*)d_out;

    float* d_whqT; cudaGetSymbolAddress((void**)&d_whqT, g_whqT);
    float* d_whp;  cudaGetSymbolAddress((void**)&d_whp,  g_whp);
    float* d_pb;   cudaGetSymbolAddress((void**)&d_pb,   g_pb);
    float* d_P;    cudaGetSymbolAddress((void**)&d_P,    g_P);

    k_vec<<<dim3(Tt, Bb), 256>>>(q, p, Wm);
    // whqT[b] = (q[b] @ Wc1) stored transposed
    gemm128<<<dim3(2, 2, Bb), 256>>>(q, (size_t)Tt*Hh, Hh,
                                     Wc1, 0, 0, Tt,
                                     d_whqT, (size_t)Tt*Tt, Hh, 1);
    // whp[b] = p[b] @ Wc2
    gemm128<<<dim3(2, 2, Bb), 256>>>(p, (size_t)Tt*Hh, Hh,
                                     Wc2, 0, 0, Tt,
                                     d_whp, (size_t)Tt*Tt, Hh, 0);
    // pb[b] = p[b] @ Wb
    gemm128<<<dim3(6, 2, Bb), 256>>>(p, (size_t)Tt*Hh, Hh,
                                     Wb, 0, 0, Hh,
                                     d_pb, (size_t)Tt*Hh, Hh, 0);
    // Sb, Sd
    gemm_bt2<<<dim3(4, 2, Bb), 256>>>(p, q, Wd, vd);
    // 4x softmax
    k_softmax<<<dim3(Tt, Bb, 4), 256>>>(vc, vm);
    // out[z] = P[z] @ q[z&63], z = type*64 + b
    gemm128<<<dim3(6, 2, 4*Bb), 256>>>(d_P, (size_t)Tt*Tt, Tt,
                                       q, (size_t)Tt*Hh, 63, Hh,
                                       out, (size_t)Tt*Hh, Tt, 0);
}